// round 1
// baseline (speedup 1.0000x reference)
#include <cuda_runtime.h>
#include <cstdint>

#define B_ 8
#define T_ 1024
#define C_ 1024
#define H_ 16
#define HS 64

// Scratch for q/k/v projections: [B*H][T][HS] each (32 MB apiece).
__device__ float g_q[(size_t)B_ * H_ * T_ * HS];
__device__ float g_k[(size_t)B_ * H_ * T_ * HS];
__device__ float g_v[(size_t)B_ * H_ * T_ * HS];

__device__ __forceinline__ uint32_t f2tf32(float f) {
    uint32_t r;
    asm("cvt.rna.tf32.f32 %0, %1;" : "=r"(r) : "f"(f));
    return r;
}

// D(16x8,f32) += A(16x8,tf32) * B(8x8,tf32)
__device__ __forceinline__ void mma8(float* d, const uint32_t* a, uint32_t b0, uint32_t b1) {
    asm volatile(
        "mma.sync.aligned.m16n8k8.row.col.f32.tf32.tf32.f32 "
        "{%0,%1,%2,%3},{%4,%5,%6,%7},{%8,%9},{%0,%1,%2,%3};\n"
        : "+f"(d[0]), "+f"(d[1]), "+f"(d[2]), "+f"(d[3])
        : "r"(a[0]), "r"(a[1]), "r"(a[2]), "r"(a[3]), "r"(b0), "r"(b1));
}

// ---------------------------------------------------------------------------
// Projection kernel: per block, Y[128 x 64] = X_tile[128 x 1024] @ W_h[1024 x 64]
// for all three of Wq/Wk/Wv (shared X tile). tf32 MMA, 256 threads (8 warps, 4x2).
// ---------------------------------------------------------------------------
#define APAD 36
#define BPAD 68

__global__ __launch_bounds__(256) void proj_kernel(
    const float* __restrict__ x, const float* __restrict__ Wq,
    const float* __restrict__ Wk, const float* __restrict__ Wv)
{
    __shared__ float As[128 * APAD];      // X tile [128][32], stride 36
    __shared__ float Bs[3 * 32 * BPAD];   // W tiles [3][32][64], stride 68

    const int tt = blockIdx.x;            // T-tile (128 rows)
    const int bh = blockIdx.y;            // b*16 + h
    const int b = bh >> 4, h = bh & 15;
    const int tid = threadIdx.x;
    const int warp = tid >> 5, lane = tid & 31;
    const int wm = warp >> 1;             // 0..3 -> rows wm*32
    const int wn = warp & 1;              // 0..1 -> cols wn*32
    const int g = lane >> 2, tg = lane & 3;

    const float* xb = x + ((size_t)(b * T_ + tt * 128)) * C_;
    const size_t woff = (size_t)h * C_ * HS;

    float acc[3][2][4][4];
#pragma unroll
    for (int m3 = 0; m3 < 3; m3++)
#pragma unroll
        for (int mt = 0; mt < 2; mt++)
#pragma unroll
            for (int nt = 0; nt < 4; nt++)
#pragma unroll
                for (int i = 0; i < 4; i++) acc[m3][mt][nt][i] = 0.f;

    for (int k0 = 0; k0 < C_; k0 += 32) {
        // Load X tile: 128 rows x 32 cols = 1024 float4, 4 per thread
#pragma unroll
        for (int i = 0; i < 4; i++) {
            int fid = tid + i * 256;
            int r = fid >> 3, c = (fid & 7) * 4;
            float4 v = *(const float4*)(xb + (size_t)r * C_ + k0 + c);
            *(float4*)(&As[r * APAD + c]) = v;
        }
        // Load W tiles: 3 x (32 x 64) = 1536 float4, 6 per thread
#pragma unroll
        for (int i = 0; i < 6; i++) {
            int fid = tid + i * 256;
            int mat = fid >> 9;
            int rem = fid & 511;
            int r = rem >> 4, c = (rem & 15) * 4;
            const float* wp = (mat == 0) ? Wq : ((mat == 1) ? Wk : Wv);
            float4 v = *(const float4*)(wp + woff + (size_t)(k0 + r) * HS + c);
            *(float4*)(&Bs[(mat * 32 + r) * BPAD + c]) = v;
        }
        __syncthreads();

#pragma unroll
        for (int ks = 0; ks < 4; ks++) {
            uint32_t a[2][4];
#pragma unroll
            for (int mt = 0; mt < 2; mt++) {
                int row = wm * 32 + mt * 16 + g;
                a[mt][0] = f2tf32(As[row * APAD + ks * 8 + tg]);
                a[mt][1] = f2tf32(As[(row + 8) * APAD + ks * 8 + tg]);
                a[mt][2] = f2tf32(As[row * APAD + ks * 8 + tg + 4]);
                a[mt][3] = f2tf32(As[(row + 8) * APAD + ks * 8 + tg + 4]);
            }
#pragma unroll
            for (int m3 = 0; m3 < 3; m3++) {
#pragma unroll
                for (int nt = 0; nt < 4; nt++) {
                    int base = (m3 * 32 + ks * 8 + tg) * BPAD + wn * 32 + nt * 8 + g;
                    uint32_t b0 = f2tf32(Bs[base]);
                    uint32_t b1 = f2tf32(Bs[base + 4 * BPAD]);
                    mma8(acc[m3][0][nt], a[0], b0, b1);
                    mma8(acc[m3][1][nt], a[1], b0, b1);
                }
            }
        }
        __syncthreads();
    }

    // Epilogue: write q/k/v [bh][T][HS]
#pragma unroll
    for (int m3 = 0; m3 < 3; m3++) {
        float* dst = (m3 == 0) ? g_q : ((m3 == 1) ? g_k : g_v);
        dst += ((size_t)bh * T_ + tt * 128) * HS;
#pragma unroll
        for (int mt = 0; mt < 2; mt++) {
            int row = wm * 32 + mt * 16 + g;
#pragma unroll
            for (int nt = 0; nt < 4; nt++) {
                int col = wn * 32 + nt * 8 + tg * 2;
                *(float2*)(dst + (size_t)row * HS + col) =
                    make_float2(acc[m3][mt][nt][0], acc[m3][mt][nt][1]);
                *(float2*)(dst + (size_t)(row + 8) * HS + col) =
                    make_float2(acc[m3][mt][nt][2], acc[m3][mt][nt][3]);
            }
        }
    }
}

// ---------------------------------------------------------------------------
// Flash attention kernel: per block = (q-tile of 64 rows, bh). 128 threads.
// Q fragments in registers (pre-scaled by 1/8), KV tiles of 64 streamed via smem,
// fp32 online softmax, tf32 MMAs for S=QK^T and O+=PV.
// ---------------------------------------------------------------------------
#define SPAD 68

__global__ __launch_bounds__(128) void attn_kernel(float* __restrict__ out)
{
    extern __shared__ float sm[];
    float* Ks  = sm;                      // [64][SPAD]
    float* Vs  = sm + 64 * SPAD;          // [64][SPAD]
    float* Ss  = sm + 2 * 64 * SPAD;      // [64][SPAD]  (S, then P)
    float* m_s = sm + 3 * 64 * SPAD;      // [64] running max
    float* l_s = m_s + 64;                // [64] running sum
    float* al_s = l_s + 64;               // [64] rescale factor

    const int qt = blockIdx.x, bh = blockIdx.y;
    const int b = bh >> 4, h = bh & 15;
    const int tid = threadIdx.x, warp = tid >> 5, lane = tid & 31;
    const int g = lane >> 2, tg = lane & 3;
    const int r0 = warp * 16 + g;         // this thread's first S/O row

    const float* qb = g_q + ((size_t)bh * T_ + qt * 64) * HS;
    const float* kb = g_k + (size_t)bh * T_ * HS;
    const float* vb = g_v + (size_t)bh * T_ * HS;

    // Q fragments (rows r0, r0+8; all 64 cols), scaled by 1/sqrt(64)
    uint32_t qf[8][4];
#pragma unroll
    for (int ks = 0; ks < 8; ks++) {
        qf[ks][0] = f2tf32(qb[(size_t)r0 * HS + ks * 8 + tg] * 0.125f);
        qf[ks][1] = f2tf32(qb[(size_t)(r0 + 8) * HS + ks * 8 + tg] * 0.125f);
        qf[ks][2] = f2tf32(qb[(size_t)r0 * HS + ks * 8 + tg + 4] * 0.125f);
        qf[ks][3] = f2tf32(qb[(size_t)(r0 + 8) * HS + ks * 8 + tg + 4] * 0.125f);
    }

    if (tid < 64) { m_s[tid] = -1e30f; l_s[tid] = 0.f; }

    float oacc[8][4];
#pragma unroll
    for (int nt = 0; nt < 8; nt++)
#pragma unroll
        for (int i = 0; i < 4; i++) oacc[nt][i] = 0.f;

    for (int j = 0; j <= qt; j++) {
        const float* kp = kb + (size_t)j * 64 * HS;
        const float* vp = vb + (size_t)j * 64 * HS;
#pragma unroll
        for (int i = 0; i < 8; i++) {
            int fid = tid + i * 128;
            int r = fid >> 4, c = (fid & 15) * 4;
            *(float4*)(&Ks[r * SPAD + c]) = *(const float4*)(kp + (size_t)r * HS + c);
            *(float4*)(&Vs[r * SPAD + c]) = *(const float4*)(vp + (size_t)r * HS + c);
        }
        __syncthreads();

        // S = Qs * K^T : each warp 16 rows x 64 cols
        float sacc[8][4];
#pragma unroll
        for (int nt = 0; nt < 8; nt++)
#pragma unroll
            for (int i = 0; i < 4; i++) sacc[nt][i] = 0.f;
#pragma unroll
        for (int ks = 0; ks < 8; ks++) {
#pragma unroll
            for (int nt = 0; nt < 8; nt++) {
                uint32_t b0 = f2tf32(Ks[(nt * 8 + g) * SPAD + ks * 8 + tg]);
                uint32_t b1 = f2tf32(Ks[(nt * 8 + g) * SPAD + ks * 8 + tg + 4]);
                mma8(sacc[nt], qf[ks], b0, b1);
            }
        }
        // Spill S to smem (C-layout -> row-major)
#pragma unroll
        for (int nt = 0; nt < 8; nt++) {
            int c = nt * 8 + tg * 2;
            *(float2*)(&Ss[r0 * SPAD + c]) = make_float2(sacc[nt][0], sacc[nt][1]);
            *(float2*)(&Ss[(r0 + 8) * SPAD + c]) = make_float2(sacc[nt][2], sacc[nt][3]);
        }
        __syncthreads();

        // Online softmax: 2 threads per row, 32 cols each
        {
            int r = tid >> 1, hf = tid & 1;
            int qrow = qt * 64 + r;
            float* srow = Ss + r * SPAD + hf * 32;
            int kvb = j * 64 + hf * 32;
            bool diag = (j == qt);
            float mx = -1e30f;
#pragma unroll
            for (int c = 0; c < 32; c++) {
                float s = srow[c];
                if (diag && (kvb + c > qrow)) s = -1e30f;
                mx = fmaxf(mx, s);
            }
            mx = fmaxf(mx, __shfl_xor_sync(0xffffffffu, mx, 1));
            float mprev = m_s[r];
            float lprev = l_s[r];
            float mnew = fmaxf(mprev, mx);
            float alpha = __expf(mprev - mnew);
            float lsum = 0.f;
#pragma unroll
            for (int c = 0; c < 32; c++) {
                float s = srow[c];
                if (diag && (kvb + c > qrow)) s = -1e30f;
                float p = __expf(s - mnew);
                srow[c] = p;
                lsum += p;
            }
            lsum += __shfl_xor_sync(0xffffffffu, lsum, 1);
            if (hf == 0) {
                m_s[r] = mnew;
                l_s[r] = alpha * lprev + lsum;
                al_s[r] = alpha;
            }
        }
        __syncthreads();

        // Rescale O, then O += P * V
        float a0 = al_s[r0], a1 = al_s[r0 + 8];
#pragma unroll
        for (int nt = 0; nt < 8; nt++) {
            oacc[nt][0] *= a0; oacc[nt][1] *= a0;
            oacc[nt][2] *= a1; oacc[nt][3] *= a1;
        }
#pragma unroll
        for (int ks = 0; ks < 8; ks++) {
            uint32_t pa[4];
            pa[0] = f2tf32(Ss[r0 * SPAD + ks * 8 + tg]);
            pa[1] = f2tf32(Ss[(r0 + 8) * SPAD + ks * 8 + tg]);
            pa[2] = f2tf32(Ss[r0 * SPAD + ks * 8 + tg + 4]);
            pa[3] = f2tf32(Ss[(r0 + 8) * SPAD + ks * 8 + tg + 4]);
#pragma unroll
            for (int nt = 0; nt < 8; nt++) {
                uint32_t b0 = f2tf32(Vs[(ks * 8 + tg) * SPAD + nt * 8 + g]);
                uint32_t b1 = f2tf32(Vs[(ks * 8 + tg + 4) * SPAD + nt * 8 + g]);
                mma8(oacc[nt], pa, b0, b1);
            }
        }
        __syncthreads();
    }

    // Final normalize + write out[b][t][h*64 + d]
    float inv0 = 1.0f / l_s[r0];
    float inv1 = 1.0f / l_s[r0 + 8];
    float* op = out + ((size_t)(b * T_ + qt * 64)) * (H_ * HS) + h * HS;
#pragma unroll
    for (int nt = 0; nt < 8; nt++) {
        int c = nt * 8 + tg * 2;
        *(float2*)(op + (size_t)r0 * (H_ * HS) + c) =
            make_float2(oacc[nt][0] * inv0, oacc[nt][1] * inv0);
        *(float2*)(op + (size_t)(r0 + 8) * (H_ * HS) + c) =
            make_float2(oacc[nt][2] * inv1, oacc[nt][3] * inv1);
    }
}

// ---------------------------------------------------------------------------
extern "C" void kernel_launch(void* const* d_in, const int* in_sizes, int n_in,
                              void* d_out, int out_size)
{
    const float* x  = (const float*)d_in[0];
    const float* Wq = (const float*)d_in[1];
    const float* Wk = (const float*)d_in[2];
    const float* Wv = (const float*)d_in[3];
    float* out = (float*)d_out;

    dim3 pg(T_ / 128, B_ * H_);
    proj_kernel<<<pg, 256>>>(x, Wq, Wk, Wv);

    int smem = (3 * 64 * SPAD + 3 * 64) * (int)sizeof(float);
    cudaFuncSetAttribute(attn_kernel, cudaFuncAttributeMaxDynamicSharedMemorySize, smem);
    dim3 ag(T_ / 64, B_ * H_);
    attn_kernel<<<ag, 128, smem>>>(out);
}

// round 2
// speedup vs baseline: 1.0005x; 1.0005x over previous
#include <cuda_runtime.h>
#include <cstdint>

#define B_ 8
#define T_ 1024
#define C_ 1024
#define H_ 16
#define HS 64

// Scratch for q/k/v projections: [B*H][T][HS] each (32 MB apiece).
__device__ float g_q[(size_t)B_ * H_ * T_ * HS];
__device__ float g_k[(size_t)B_ * H_ * T_ * HS];
__device__ float g_v[(size_t)B_ * H_ * T_ * HS];

__device__ __forceinline__ uint32_t f2tf32(float f) {
    uint32_t r;
    asm("cvt.rna.tf32.f32 %0, %1;" : "=r"(r) : "f"(f));
    return r;
}

// D(16x8,f32) += A(16x8,tf32) * B(8x8,tf32)
__device__ __forceinline__ void mma8(float* d, const uint32_t* a, uint32_t b0, uint32_t b1) {
    asm volatile(
        "mma.sync.aligned.m16n8k8.row.col.f32.tf32.tf32.f32 "
        "{%0,%1,%2,%3},{%4,%5,%6,%7},{%8,%9},{%0,%1,%2,%3};\n"
        : "+f"(d[0]), "+f"(d[1]), "+f"(d[2]), "+f"(d[3])
        : "r"(a[0]), "r"(a[1]), "r"(a[2]), "r"(a[3]), "r"(b0), "r"(b1));
}

// ---------------------------------------------------------------------------
// Projection kernel: per block, Y[128 x 64] = X_tile[128 x 1024] @ W_h[1024 x 64]
// for all three of Wq/Wk/Wv (shared X tile). tf32 MMA, 256 threads (8 warps, 4x2).
// ---------------------------------------------------------------------------
#define APAD 36
#define BPAD 68

__global__ __launch_bounds__(256) void proj_kernel(
    const float* __restrict__ x, const float* __restrict__ Wq,
    const float* __restrict__ Wk, const float* __restrict__ Wv)
{
    __shared__ float As[128 * APAD];      // X tile [128][32], stride 36
    __shared__ float Bs[3 * 32 * BPAD];   // W tiles [3][32][64], stride 68

    const int tt = blockIdx.x;            // T-tile (128 rows)
    const int bh = blockIdx.y;            // b*16 + h
    const int b = bh >> 4, h = bh & 15;
    const int tid = threadIdx.x;
    const int warp = tid >> 5, lane = tid & 31;
    const int wm = warp >> 1;             // 0..3 -> rows wm*32
    const int wn = warp & 1;              // 0..1 -> cols wn*32
    const int g = lane >> 2, tg = lane & 3;

    const float* xb = x + ((size_t)(b * T_ + tt * 128)) * C_;
    const size_t woff = (size_t)h * C_ * HS;

    float acc[3][2][4][4];
#pragma unroll
    for (int m3 = 0; m3 < 3; m3++)
#pragma unroll
        for (int mt = 0; mt < 2; mt++)
#pragma unroll
            for (int nt = 0; nt < 4; nt++)
#pragma unroll
                for (int i = 0; i < 4; i++) acc[m3][mt][nt][i] = 0.f;

    for (int k0 = 0; k0 < C_; k0 += 32) {
        // Load X tile: 128 rows x 32 cols = 1024 float4, 4 per thread
#pragma unroll
        for (int i = 0; i < 4; i++) {
            int fid = tid + i * 256;
            int r = fid >> 3, c = (fid & 7) * 4;
            float4 v = *(const float4*)(xb + (size_t)r * C_ + k0 + c);
            *(float4*)(&As[r * APAD + c]) = v;
        }
        // Load W tiles: 3 x (32 x 64) = 1536 float4, 6 per thread
#pragma unroll
        for (int i = 0; i < 6; i++) {
            int fid = tid + i * 256;
            int mat = fid >> 9;
            int rem = fid & 511;
            int r = rem >> 4, c = (rem & 15) * 4;
            const float* wp = (mat == 0) ? Wq : ((mat == 1) ? Wk : Wv);
            float4 v = *(const float4*)(wp + woff + (size_t)(k0 + r) * HS + c);
            *(float4*)(&Bs[(mat * 32 + r) * BPAD + c]) = v;
        }
        __syncthreads();

#pragma unroll
        for (int ks = 0; ks < 4; ks++) {
            uint32_t a[2][4];
#pragma unroll
            for (int mt = 0; mt < 2; mt++) {
                int row = wm * 32 + mt * 16 + g;
                a[mt][0] = f2tf32(As[row * APAD + ks * 8 + tg]);
                a[mt][1] = f2tf32(As[(row + 8) * APAD + ks * 8 + tg]);
                a[mt][2] = f2tf32(As[row * APAD + ks * 8 + tg + 4]);
                a[mt][3] = f2tf32(As[(row + 8) * APAD + ks * 8 + tg + 4]);
            }
#pragma unroll
            for (int m3 = 0; m3 < 3; m3++) {
#pragma unroll
                for (int nt = 0; nt < 4; nt++) {
                    int base = (m3 * 32 + ks * 8 + tg) * BPAD + wn * 32 + nt * 8 + g;
                    uint32_t b0 = f2tf32(Bs[base]);
                    uint32_t b1 = f2tf32(Bs[base + 4 * BPAD]);
                    mma8(acc[m3][0][nt], a[0], b0, b1);
                    mma8(acc[m3][1][nt], a[1], b0, b1);
                }
            }
        }
        __syncthreads();
    }

    // Epilogue: write q/k/v [bh][T][HS]
#pragma unroll
    for (int m3 = 0; m3 < 3; m3++) {
        float* dst = (m3 == 0) ? g_q : ((m3 == 1) ? g_k : g_v);
        dst += ((size_t)bh * T_ + tt * 128) * HS;
#pragma unroll
        for (int mt = 0; mt < 2; mt++) {
            int row = wm * 32 + mt * 16 + g;
#pragma unroll
            for (int nt = 0; nt < 4; nt++) {
                int col = wn * 32 + nt * 8 + tg * 2;
                *(float2*)(dst + (size_t)row * HS + col) =
                    make_float2(acc[m3][mt][nt][0], acc[m3][mt][nt][1]);
                *(float2*)(dst + (size_t)(row + 8) * HS + col) =
                    make_float2(acc[m3][mt][nt][2], acc[m3][mt][nt][3]);
            }
        }
    }
}

// ---------------------------------------------------------------------------
// Flash attention kernel: per block = (q-tile of 64 rows, bh). 128 threads.
// Q fragments in registers (pre-scaled by 1/8), KV tiles of 64 streamed via smem,
// fp32 online softmax, tf32 MMAs for S=QK^T and O+=PV.
// ---------------------------------------------------------------------------
#define SPAD 68

__global__ __launch_bounds__(128) void attn_kernel(float* __restrict__ out)
{
    extern __shared__ float sm[];
    float* Ks  = sm;                      // [64][SPAD]
    float* Vs  = sm + 64 * SPAD;          // [64][SPAD]
    float* Ss  = sm + 2 * 64 * SPAD;      // [64][SPAD]  (S, then P)
    float* m_s = sm + 3 * 64 * SPAD;      // [64] running max
    float* l_s = m_s + 64;                // [64] running sum
    float* al_s = l_s + 64;               // [64] rescale factor

    const int qt = blockIdx.x, bh = blockIdx.y;
    const int b = bh >> 4, h = bh & 15;
    const int tid = threadIdx.x, warp = tid >> 5, lane = tid & 31;
    const int g = lane >> 2, tg = lane & 3;
    const int r0 = warp * 16 + g;         // this thread's first S/O row

    const float* qb = g_q + ((size_t)bh * T_ + qt * 64) * HS;
    const float* kb = g_k + (size_t)bh * T_ * HS;
    const float* vb = g_v + (size_t)bh * T_ * HS;

    // Q fragments (rows r0, r0+8; all 64 cols), scaled by 1/sqrt(64)
    uint32_t qf[8][4];
#pragma unroll
    for (int ks = 0; ks < 8; ks++) {
        qf[ks][0] = f2tf32(qb[(size_t)r0 * HS + ks * 8 + tg] * 0.125f);
        qf[ks][1] = f2tf32(qb[(size_t)(r0 + 8) * HS + ks * 8 + tg] * 0.125f);
        qf[ks][2] = f2tf32(qb[(size_t)r0 * HS + ks * 8 + tg + 4] * 0.125f);
        qf[ks][3] = f2tf32(qb[(size_t)(r0 + 8) * HS + ks * 8 + tg + 4] * 0.125f);
    }

    if (tid < 64) { m_s[tid] = -1e30f; l_s[tid] = 0.f; }

    float oacc[8][4];
#pragma unroll
    for (int nt = 0; nt < 8; nt++)
#pragma unroll
        for (int i = 0; i < 4; i++) oacc[nt][i] = 0.f;

    for (int j = 0; j <= qt; j++) {
        const float* kp = kb + (size_t)j * 64 * HS;
        const float* vp = vb + (size_t)j * 64 * HS;
#pragma unroll
        for (int i = 0; i < 8; i++) {
            int fid = tid + i * 128;
            int r = fid >> 4, c = (fid & 15) * 4;
            *(float4*)(&Ks[r * SPAD + c]) = *(const float4*)(kp + (size_t)r * HS + c);
            *(float4*)(&Vs[r * SPAD + c]) = *(const float4*)(vp + (size_t)r * HS + c);
        }
        __syncthreads();

        // S = Qs * K^T : each warp 16 rows x 64 cols
        float sacc[8][4];
#pragma unroll
        for (int nt = 0; nt < 8; nt++)
#pragma unroll
            for (int i = 0; i < 4; i++) sacc[nt][i] = 0.f;
#pragma unroll
        for (int ks = 0; ks < 8; ks++) {
#pragma unroll
            for (int nt = 0; nt < 8; nt++) {
                uint32_t b0 = f2tf32(Ks[(nt * 8 + g) * SPAD + ks * 8 + tg]);
                uint32_t b1 = f2tf32(Ks[(nt * 8 + g) * SPAD + ks * 8 + tg + 4]);
                mma8(sacc[nt], qf[ks], b0, b1);
            }
        }
        // Spill S to smem (C-layout -> row-major)
#pragma unroll
        for (int nt = 0; nt < 8; nt++) {
            int c = nt * 8 + tg * 2;
            *(float2*)(&Ss[r0 * SPAD + c]) = make_float2(sacc[nt][0], sacc[nt][1]);
            *(float2*)(&Ss[(r0 + 8) * SPAD + c]) = make_float2(sacc[nt][2], sacc[nt][3]);
        }
        __syncthreads();

        // Online softmax: 2 threads per row, 32 cols each
        {
            int r = tid >> 1, hf = tid & 1;
            int qrow = qt * 64 + r;
            float* srow = Ss + r * SPAD + hf * 32;
            int kvb = j * 64 + hf * 32;
            bool diag = (j == qt);
            float mx = -1e30f;
#pragma unroll
            for (int c = 0; c < 32; c++) {
                float s = srow[c];
                if (diag && (kvb + c > qrow)) s = -1e30f;
                mx = fmaxf(mx, s);
            }
            mx = fmaxf(mx, __shfl_xor_sync(0xffffffffu, mx, 1));
            float mprev = m_s[r];
            float lprev = l_s[r];
            float mnew = fmaxf(mprev, mx);
            float alpha = __expf(mprev - mnew);
            float lsum = 0.f;
#pragma unroll
            for (int c = 0; c < 32; c++) {
                float s = srow[c];
                if (diag && (kvb + c > qrow)) s = -1e30f;
                float p = __expf(s - mnew);
                srow[c] = p;
                lsum += p;
            }
            lsum += __shfl_xor_sync(0xffffffffu, lsum, 1);
            if (hf == 0) {
                m_s[r] = mnew;
                l_s[r] = alpha * lprev + lsum;
                al_s[r] = alpha;
            }
        }
        __syncthreads();

        // Rescale O, then O += P * V
        float a0 = al_s[r0], a1 = al_s[r0 + 8];
#pragma unroll
        for (int nt = 0; nt < 8; nt++) {
            oacc[nt][0] *= a0; oacc[nt][1] *= a0;
            oacc[nt][2] *= a1; oacc[nt][3] *= a1;
        }
#pragma unroll
        for (int ks = 0; ks < 8; ks++) {
            uint32_t pa[4];
            pa[0] = f2tf32(Ss[r0 * SPAD + ks * 8 + tg]);
            pa[1] = f2tf32(Ss[(r0 + 8) * SPAD + ks * 8 + tg]);
            pa[2] = f2tf32(Ss[r0 * SPAD + ks * 8 + tg + 4]);
            pa[3] = f2tf32(Ss[(r0 + 8) * SPAD + ks * 8 + tg + 4]);
#pragma unroll
            for (int nt = 0; nt < 8; nt++) {
                uint32_t b0 = f2tf32(Vs[(ks * 8 + tg) * SPAD + nt * 8 + g]);
                uint32_t b1 = f2tf32(Vs[(ks * 8 + tg + 4) * SPAD + nt * 8 + g]);
                mma8(oacc[nt], pa, b0, b1);
            }
        }
        __syncthreads();
    }

    // Final normalize + write out[b][t][h*64 + d]
    float inv0 = 1.0f / l_s[r0];
    float inv1 = 1.0f / l_s[r0 + 8];
    float* op = out + ((size_t)(b * T_ + qt * 64)) * (H_ * HS) + h * HS;
#pragma unroll
    for (int nt = 0; nt < 8; nt++) {
        int c = nt * 8 + tg * 2;
        *(float2*)(op + (size_t)r0 * (H_ * HS) + c) =
            make_float2(oacc[nt][0] * inv0, oacc[nt][1] * inv0);
        *(float2*)(op + (size_t)(r0 + 8) * (H_ * HS) + c) =
            make_float2(oacc[nt][2] * inv1, oacc[nt][3] * inv1);
    }
}

// ---------------------------------------------------------------------------
extern "C" void kernel_launch(void* const* d_in, const int* in_sizes, int n_in,
                              void* d_out, int out_size)
{
    const float* x  = (const float*)d_in[0];
    const float* Wq = (const float*)d_in[1];
    const float* Wk = (const float*)d_in[2];
    const float* Wv = (const float*)d_in[3];
    float* out = (float*)d_out;

    dim3 pg(T_ / 128, B_ * H_);
    proj_kernel<<<pg, 256>>>(x, Wq, Wk, Wv);

    int smem = (3 * 64 * SPAD + 3 * 64) * (int)sizeof(float);
    cudaFuncSetAttribute(attn_kernel, cudaFuncAttributeMaxDynamicSharedMemorySize, smem);
    dim3 ag(T_ / 64, B_ * H_);
    attn_kernel<<<ag, 128, smem>>>(out);
}

// round 4
// speedup vs baseline: 1.2550x; 1.2543x over previous
#include <cuda_runtime.h>
#include <cstdint>

#define B_ 8
#define T_ 1024
#define C_ 1024
#define H_ 16
#define HS 64

__device__ float g_q[(size_t)B_ * H_ * T_ * HS];
__device__ float g_k[(size_t)B_ * H_ * T_ * HS];
__device__ float g_v[(size_t)B_ * H_ * T_ * HS];
__device__ float g_xp[(size_t)B_ * T_ * C_];          // tf32-rounded X
__device__ float g_wt[(size_t)3 * H_ * HS * C_];      // tf32-rounded W, [mh*64+n][k]

__device__ __forceinline__ uint32_t f2tf32(float f) {
    uint32_t r; asm("cvt.rna.tf32.f32 %0, %1;" : "=r"(r) : "f"(f)); return r;
}
__device__ __forceinline__ float tf32f(float f) { return __uint_as_float(f2tf32(f)); }
__device__ __forceinline__ uint32_t smem_u32(const void* p) {
    uint32_t a;
    asm("{ .reg .u64 t; cvta.to.shared.u64 t, %1; cvt.u32.u64 %0, t; }" : "=r"(a) : "l"(p));
    return a;
}
static __device__ __forceinline__ void cp16(uint32_t dst, const void* src) {
    asm volatile("cp.async.cg.shared.global [%0], [%1], 16;" :: "r"(dst), "l"(src) : "memory");
}
#define CP_COMMIT() asm volatile("cp.async.commit_group;" ::: "memory")
#define CP_WAIT(n)  asm volatile("cp.async.wait_group %0;" :: "n"(n) : "memory")

__device__ __forceinline__ void mma8(float* d, const uint32_t* a, uint32_t b0, uint32_t b1) {
    asm volatile("mma.sync.aligned.m16n8k8.row.col.f32.tf32.tf32.f32 "
        "{%0,%1,%2,%3},{%4,%5,%6,%7},{%8,%9},{%0,%1,%2,%3};\n"
        : "+f"(d[0]), "+f"(d[1]), "+f"(d[2]), "+f"(d[3])
        : "r"(a[0]), "r"(a[1]), "r"(a[2]), "r"(a[3]), "r"(b0), "r"(b1));
}

// ---------------- prep: pre-round operands to tf32 ----------------
__global__ void xprep(const float* __restrict__ x) {
    size_t i = ((size_t)blockIdx.x * 256 + threadIdx.x) * 4;
    float4 v = *(const float4*)(x + i);
    v.x = tf32f(v.x); v.y = tf32f(v.y); v.z = tf32f(v.z); v.w = tf32f(v.w);
    *(float4*)(g_xp + i) = v;
}
__global__ void wprep(const float* __restrict__ Wq, const float* __restrict__ Wk,
                      const float* __restrict__ Wv) {
    __shared__ float t[64][65];
    int kt = blockIdx.x, mh = blockIdx.y;          // kt: 64-wide k tile, mh = m3*16+h
    int m3 = mh >> 4, h = mh & 15;
    const float* W = (m3 == 0) ? Wq : ((m3 == 1) ? Wk : Wv);
    const float* src = W + (size_t)h * C_ * HS + (size_t)kt * 64 * HS;
    int tid = threadIdx.x;
#pragma unroll
    for (int i = 0; i < 16; i++) {
        int k = i * 4 + (tid >> 6), n = tid & 63;
        t[k][n] = src[(size_t)k * HS + n];
    }
    __syncthreads();
    float* dst = g_wt + (size_t)(mh * 64) * C_ + (size_t)kt * 64;
#pragma unroll
    for (int i = 0; i < 16; i++) {
        int n = i * 4 + (tid >> 6), kk = tid & 63;
        dst[(size_t)n * C_ + kk] = tf32f(t[kk][n]);
    }
}

// ---------------- projection: 128x128-tile double-buffered tf32 GEMM ----------------
#define PAD 36
#define TILE_F (128 * PAD)

__global__ __launch_bounds__(256) void proj2() {
    extern __shared__ float sm[];
    float* As = sm;                    // [2][128][PAD]
    float* Bs = sm + 2 * TILE_F;       // [2][128][PAD]
    uint32_t sA = smem_u32(As), sB = smem_u32(Bs);

    const int tid = threadIdx.x, warp = tid >> 5, lane = tid & 31;
    const int g = lane >> 2, tg = lane & 3;
    const int wm = warp >> 2, wn = warp & 3;       // 2x4 warp grid: 64 rows x 32 cols
    const int mt_ = blockIdx.x, b = mt_ >> 3, tt = mt_ & 7;
    const int nb = blockIdx.y, m3 = nb >> 3, hp = nb & 7;

    const float* Arow = g_xp + (size_t)(b * T_ + tt * 128) * C_;
    const float* Brow = g_wt + (size_t)((m3 * 16 + hp * 2) * 64) * C_;
    const int sr = tid >> 1;                        // staging row pair base
    // staging: 4 float4 for A + 4 for B per thread per chunk
    const int srows[4] = { (tid + 0) >> 3 >> 0, 0, 0, 0 };   // placeholder (unused)

    float acc[4][4][4];
#pragma unroll
    for (int i = 0; i < 4; i++)
#pragma unroll
        for (int j = 0; j < 4; j++)
#pragma unroll
            for (int e = 0; e < 4; e++) acc[i][j][e] = 0.f;

    auto stage = [&](int buf, int k0) {
#pragma unroll
        for (int i = 0; i < 4; i++) {
            int fid = tid + i * 256;               // 0..1023
            int r = fid >> 3, c = (fid & 7) * 4;
            cp16(sA + (buf * TILE_F + r * PAD + c) * 4, Arow + (size_t)r * C_ + k0 + c);
            cp16(sB + (buf * TILE_F + r * PAD + c) * 4, Brow + (size_t)r * C_ + k0 + c);
        }
        CP_COMMIT();
    };

    stage(0, 0);
    for (int c = 0; c < 32; c++) {
        const int buf = c & 1;
        if (c < 31) stage(buf ^ 1, (c + 1) * 32);
        if (c < 31) CP_WAIT(1); else CP_WAIT(0);
        __syncthreads();

        const float* A = As + buf * TILE_F;
        const float* Bt = Bs + buf * TILE_F;
#pragma unroll
        for (int ks = 0; ks < 4; ks++) {
            uint32_t a[4][4];
#pragma unroll
            for (int mt = 0; mt < 4; mt++) {
                int row = wm * 64 + mt * 16 + g;
                a[mt][0] = __float_as_uint(A[row * PAD + ks * 8 + tg]);
                a[mt][1] = __float_as_uint(A[(row + 8) * PAD + ks * 8 + tg]);
                a[mt][2] = __float_as_uint(A[row * PAD + ks * 8 + tg + 4]);
                a[mt][3] = __float_as_uint(A[(row + 8) * PAD + ks * 8 + tg + 4]);
            }
            uint32_t bb[4][2];
#pragma unroll
            for (int nt = 0; nt < 4; nt++) {
                int n = wn * 32 + nt * 8 + g;
                bb[nt][0] = __float_as_uint(Bt[n * PAD + ks * 8 + tg]);
                bb[nt][1] = __float_as_uint(Bt[n * PAD + ks * 8 + tg + 4]);
            }
#pragma unroll
            for (int mt = 0; mt < 4; mt++)
#pragma unroll
                for (int nt = 0; nt < 4; nt++)
                    mma8(acc[mt][nt], a[mt], bb[nt][0], bb[nt][1]);
        }
        __syncthreads();
    }

    // Epilogue: pre-round outputs to tf32 so attn can skip cvt on K/V.
    float* base = (m3 == 0) ? g_q : ((m3 == 1) ? g_k : g_v);
#pragma unroll
    for (int mt = 0; mt < 4; mt++) {
        int row = wm * 64 + mt * 16 + g;
        int t = tt * 128 + row;
#pragma unroll
        for (int nt = 0; nt < 4; nt++) {
            int col = wn * 32 + nt * 8 + tg * 2;
            int hsel = col >> 6, d = col & 63;
            int bh = b * H_ + hp * 2 + hsel;
            float* dst = base + ((size_t)bh * T_ + t) * HS + d;
            *(float2*)dst = make_float2(tf32f(acc[mt][nt][0]), tf32f(acc[mt][nt][1]));
            *(float2*)(dst + 8 * HS) = make_float2(tf32f(acc[mt][nt][2]), tf32f(acc[mt][nt][3]));
        }
    }
}

// ---------------- flash attention v2: in-reg softmax + cp.async double buffer ----------------
#define SPAD 68
#define TS (64 * SPAD)

__global__ __launch_bounds__(128) void attn2(float* __restrict__ out)
{
    extern __shared__ float sm[];
    // layout: K0 V0 K1 V1 Ps  (each 64*SPAD floats)
    uint32_t sbase = smem_u32(sm);
    float* Ps = sm + 4 * TS;

    const int qt = blockIdx.x, bh = blockIdx.y;
    const int b = bh >> 4, h = bh & 15;
    const int tid = threadIdx.x, warp = tid >> 5, lane = tid & 31;
    const int g = lane >> 2, tg = lane & 3;
    const int r0 = warp * 16 + g;

    const float* qb = g_q + ((size_t)bh * T_ + qt * 64) * HS;
    const float* kb = g_k + (size_t)bh * T_ * HS;
    const float* vb = g_v + (size_t)bh * T_ * HS;

    uint32_t qf[8][4];
#pragma unroll
    for (int ks = 0; ks < 8; ks++) {
        qf[ks][0] = f2tf32(qb[(size_t)r0 * HS + ks * 8 + tg] * 0.125f);
        qf[ks][1] = f2tf32(qb[(size_t)(r0 + 8) * HS + ks * 8 + tg] * 0.125f);
        qf[ks][2] = f2tf32(qb[(size_t)r0 * HS + ks * 8 + tg + 4] * 0.125f);
        qf[ks][3] = f2tf32(qb[(size_t)(r0 + 8) * HS + ks * 8 + tg + 4] * 0.125f);
    }

    float m0 = -1e30f, m1 = -1e30f, l0 = 0.f, l1 = 0.f;
    float oacc[8][4];
#pragma unroll
    for (int nt = 0; nt < 8; nt++)
#pragma unroll
        for (int i = 0; i < 4; i++) oacc[nt][i] = 0.f;

    auto stageKV = [&](int buf, int j) {
        const float* kp = kb + (size_t)j * 64 * HS;
        const float* vp = vb + (size_t)j * 64 * HS;
        uint32_t kofs = sbase + (buf * 2 * TS) * 4;
        uint32_t vofs = kofs + TS * 4;
#pragma unroll
        for (int i = 0; i < 8; i++) {
            int fid = tid + i * 128;
            int r = fid >> 4, c = (fid & 15) * 4;
            cp16(kofs + (r * SPAD + c) * 4, kp + (size_t)r * HS + c);
            cp16(vofs + (r * SPAD + c) * 4, vp + (size_t)r * HS + c);
        }
        CP_COMMIT();
    };

    stageKV(0, 0);
    for (int j = 0; j <= qt; j++) {
        const int buf = j & 1;
        if (j < qt) stageKV(buf ^ 1, j + 1);
        if (j < qt) CP_WAIT(1); else CP_WAIT(0);
        __syncthreads();

        const float* Ks = sm + buf * 2 * TS;
        const float* Vs = Ks + TS;

        // S = Q K^T
        float sacc[8][4];
#pragma unroll
        for (int nt = 0; nt < 8; nt++)
#pragma unroll
            for (int i = 0; i < 4; i++) sacc[nt][i] = 0.f;
#pragma unroll
        for (int ks = 0; ks < 8; ks++) {
#pragma unroll
            for (int nt = 0; nt < 8; nt++) {
                uint32_t b0 = __float_as_uint(Ks[(nt * 8 + g) * SPAD + ks * 8 + tg]);
                uint32_t b1 = __float_as_uint(Ks[(nt * 8 + g) * SPAD + ks * 8 + tg + 4]);
                mma8(sacc[nt], qf[ks], b0, b1);
            }
        }

        // Causal mask on diagonal tile (local row vs local col)
        if (j == qt) {
#pragma unroll
            for (int nt = 0; nt < 8; nt++) {
#pragma unroll
                for (int e = 0; e < 2; e++) {
                    int col = nt * 8 + tg * 2 + e;
                    if (col > r0)     sacc[nt][e]     = -1e30f;
                    if (col > r0 + 8) sacc[nt][2 + e] = -1e30f;
                }
            }
        }

        // In-register online softmax (rows r0, r0+8; reduce over tg lanes)
        float mx0 = -1e30f, mx1 = -1e30f;
#pragma unroll
        for (int nt = 0; nt < 8; nt++) {
            mx0 = fmaxf(mx0, fmaxf(sacc[nt][0], sacc[nt][1]));
            mx1 = fmaxf(mx1, fmaxf(sacc[nt][2], sacc[nt][3]));
        }
        mx0 = fmaxf(mx0, __shfl_xor_sync(0xffffffffu, mx0, 1));
        mx0 = fmaxf(mx0, __shfl_xor_sync(0xffffffffu, mx0, 2));
        mx1 = fmaxf(mx1, __shfl_xor_sync(0xffffffffu, mx1, 1));
        mx1 = fmaxf(mx1, __shfl_xor_sync(0xffffffffu, mx1, 2));

        float mn0 = fmaxf(m0, mx0), mn1 = fmaxf(m1, mx1);
        float al0 = __expf(m0 - mn0), al1 = __expf(m1 - mn1);
        float ls0 = 0.f, ls1 = 0.f;
#pragma unroll
        for (int nt = 0; nt < 8; nt++) {
            float p0 = __expf(sacc[nt][0] - mn0);
            float p1 = __expf(sacc[nt][1] - mn0);
            float p2 = __expf(sacc[nt][2] - mn1);
            float p3 = __expf(sacc[nt][3] - mn1);
            sacc[nt][0] = p0; sacc[nt][1] = p1; sacc[nt][2] = p2; sacc[nt][3] = p3;
            ls0 += p0 + p1; ls1 += p2 + p3;
        }
        ls0 += __shfl_xor_sync(0xffffffffu, ls0, 1);
        ls0 += __shfl_xor_sync(0xffffffffu, ls0, 2);
        ls1 += __shfl_xor_sync(0xffffffffu, ls1, 1);
        ls1 += __shfl_xor_sync(0xffffffffu, ls1, 2);
        l0 = al0 * l0 + ls0; l1 = al1 * l1 + ls1;
        m0 = mn0; m1 = mn1;

        // Rescale O
#pragma unroll
        for (int nt = 0; nt < 8; nt++) {
            oacc[nt][0] *= al0; oacc[nt][1] *= al0;
            oacc[nt][2] *= al1; oacc[nt][3] *= al1;
        }

        // Warp-local P transpose through smem (rows owned by this warp only)
#pragma unroll
        for (int nt = 0; nt < 8; nt++) {
            int c = nt * 8 + tg * 2;
            *(float2*)(&Ps[r0 * SPAD + c]) = make_float2(sacc[nt][0], sacc[nt][1]);
            *(float2*)(&Ps[(r0 + 8) * SPAD + c]) = make_float2(sacc[nt][2], sacc[nt][3]);
        }
        __syncwarp();

        // O += P V
#pragma unroll
        for (int ks = 0; ks < 8; ks++) {
            uint32_t pa[4];
            pa[0] = f2tf32(Ps[r0 * SPAD + ks * 8 + tg]);
            pa[1] = f2tf32(Ps[(r0 + 8) * SPAD + ks * 8 + tg]);
            pa[2] = f2tf32(Ps[r0 * SPAD + ks * 8 + tg + 4]);
            pa[3] = f2tf32(Ps[(r0 + 8) * SPAD + ks * 8 + tg + 4]);
#pragma unroll
            for (int nt = 0; nt < 8; nt++) {
                uint32_t b0 = __float_as_uint(Vs[(ks * 8 + tg) * SPAD + nt * 8 + g]);
                uint32_t b1 = __float_as_uint(Vs[(ks * 8 + tg + 4) * SPAD + nt * 8 + g]);
                mma8(oacc[nt], pa, b0, b1);
            }
        }
        __syncthreads();
    }

    float inv0 = 1.0f / l0, inv1 = 1.0f / l1;
    float* op = out + ((size_t)(b * T_ + qt * 64)) * (H_ * HS) + h * HS;
#pragma unroll
    for (int nt = 0; nt < 8; nt++) {
        int c = nt * 8 + tg * 2;
        *(float2*)(op + (size_t)r0 * (H_ * HS) + c) =
            make_float2(oacc[nt][0] * inv0, oacc[nt][1] * inv0);
        *(float2*)(op + (size_t)(r0 + 8) * (H_ * HS) + c) =
            make_float2(oacc[nt][2] * inv1, oacc[nt][3] * inv1);
    }
}

// ---------------------------------------------------------------------------
extern "C" void kernel_launch(void* const* d_in, const int* in_sizes, int n_in,
                              void* d_out, int out_size)
{
    const float* x  = (const float*)d_in[0];
    const float* Wq = (const float*)d_in[1];
    const float* Wk = (const float*)d_in[2];
    const float* Wv = (const float*)d_in[3];
    float* out = (float*)d_out;

    xprep<<<(B_ * T_ * C_) / 1024, 256>>>(x);
    wprep<<<dim3(16, 48), 256>>>(Wq, Wk, Wv);

    int psmem = 4 * TILE_F * (int)sizeof(float);
    cudaFuncSetAttribute(proj2, cudaFuncAttributeMaxDynamicSharedMemorySize, psmem);
    proj2<<<dim3(64, 24), 256, psmem>>>();

    int asmem = 5 * TS * (int)sizeof(float);
    cudaFuncSetAttribute(attn2, cudaFuncAttributeMaxDynamicSharedMemorySize, asmem);
    attn2<<<dim3(T_ / 64, B_ * H_), 128, asmem>>>(out);
}

// round 5
// speedup vs baseline: 1.3546x; 1.0794x over previous
#include <cuda_runtime.h>
#include <cstdint>

#define B_ 8
#define T_ 1024
#define C_ 1024
#define H_ 16
#define HS 64

__device__ float g_q[(size_t)B_ * H_ * T_ * HS];
__device__ float g_k[(size_t)B_ * H_ * T_ * HS];
__device__ float g_v[(size_t)B_ * H_ * T_ * HS];
__device__ float g_xp[(size_t)B_ * T_ * C_];          // tf32-rounded X
__device__ float g_wt[(size_t)3 * H_ * HS * C_];      // tf32-rounded W^T, [mh*64+n][k]

__device__ __forceinline__ uint32_t f2tf32(float f) {
    uint32_t r; asm("cvt.rna.tf32.f32 %0, %1;" : "=r"(r) : "f"(f)); return r;
}
__device__ __forceinline__ float tf32f(float f) { return __uint_as_float(f2tf32(f)); }
__device__ __forceinline__ uint32_t smem_u32(const void* p) {
    uint32_t a;
    asm("{ .reg .u64 t; cvta.to.shared.u64 t, %1; cvt.u32.u64 %0, t; }" : "=r"(a) : "l"(p));
    return a;
}
static __device__ __forceinline__ void cp16(uint32_t dst, const void* src) {
    asm volatile("cp.async.cg.shared.global [%0], [%1], 16;" :: "r"(dst), "l"(src) : "memory");
}
#define CP_COMMIT() asm volatile("cp.async.commit_group;" ::: "memory")
#define CP_WAIT(n)  asm volatile("cp.async.wait_group %0;" :: "n"(n) : "memory")

__device__ __forceinline__ void mma8(float* d, const uint32_t* a, uint32_t b0, uint32_t b1) {
    asm volatile("mma.sync.aligned.m16n8k8.row.col.f32.tf32.tf32.f32 "
        "{%0,%1,%2,%3},{%4,%5,%6,%7},{%8,%9},{%0,%1,%2,%3};\n"
        : "+f"(d[0]), "+f"(d[1]), "+f"(d[2]), "+f"(d[3])
        : "r"(a[0]), "r"(a[1]), "r"(a[2]), "r"(a[3]), "r"(b0), "r"(b1));
}

// ---------------- prep ----------------
__global__ void xprep(const float* __restrict__ x) {
    size_t i = ((size_t)blockIdx.x * 256 + threadIdx.x) * 4;
    float4 v = *(const float4*)(x + i);
    v.x = tf32f(v.x); v.y = tf32f(v.y); v.z = tf32f(v.z); v.w = tf32f(v.w);
    *(float4*)(g_xp + i) = v;
}
__global__ void wprep(const float* __restrict__ Wq, const float* __restrict__ Wk,
                      const float* __restrict__ Wv) {
    __shared__ float t[64][65];
    int kt = blockIdx.x, mh = blockIdx.y;
    int m3 = mh >> 4, h = mh & 15;
    const float* W = (m3 == 0) ? Wq : ((m3 == 1) ? Wk : Wv);
    const float* src = W + (size_t)h * C_ * HS + (size_t)kt * 64 * HS;
    int tid = threadIdx.x;
#pragma unroll
    for (int i = 0; i < 16; i++) {
        int k = i * 4 + (tid >> 6), n = tid & 63;
        t[k][n] = src[(size_t)k * HS + n];
    }
    __syncthreads();
    float* dst = g_wt + (size_t)(mh * 64) * C_ + (size_t)kt * 64;
#pragma unroll
    for (int i = 0; i < 16; i++) {
        int n = i * 4 + (tid >> 6), kk = tid & 63;
        dst[(size_t)n * C_ + kk] = tf32f(t[kk][n]);
    }
}

// ---------------- proj3: 128x128 tile, 4 warps of 64x64, double-buffered ----------------
#define PAD 36
#define PTILE (128 * PAD)

__global__ __launch_bounds__(128) void proj3() {
    extern __shared__ float sm[];
    float* As = sm;                    // [2][128][PAD]
    float* Bs = sm + 2 * PTILE;        // [2][128][PAD]
    uint32_t sA = smem_u32(As), sB = smem_u32(Bs);

    const int tid = threadIdx.x, warp = tid >> 5, lane = tid & 31;
    const int g = lane >> 2, tg = lane & 3;
    const int wm = warp >> 1, wn = warp & 1;        // 2x2 warp grid, 64x64 each
    const int mtile = blockIdx.x, b = mtile >> 3, tt = mtile & 7;
    const int nb = blockIdx.y, m3 = nb >> 3, hp = nb & 7;

    const float* Arow = g_xp + (size_t)(b * T_ + tt * 128) * C_;
    const float* Brow = g_wt + (size_t)((m3 * 16 + hp * 2) * 64) * C_;

    float acc[4][8][4];
#pragma unroll
    for (int i = 0; i < 4; i++)
#pragma unroll
        for (int jn = 0; jn < 8; jn++)
#pragma unroll
            for (int e = 0; e < 4; e++) acc[i][jn][e] = 0.f;

    auto stage = [&](int buf, int k0) {
#pragma unroll
        for (int i = 0; i < 8; i++) {
            int fid = tid + i * 128;               // 0..1023
            int r = fid >> 3, cc = (fid & 7) * 4;
            cp16(sA + (buf * PTILE + r * PAD + cc) * 4, Arow + (size_t)r * C_ + k0 + cc);
            cp16(sB + (buf * PTILE + r * PAD + cc) * 4, Brow + (size_t)r * C_ + k0 + cc);
        }
        CP_COMMIT();
    };

    stage(0, 0);
    for (int kc = 0; kc < 32; kc++) {
        const int buf = kc & 1;
        if (kc < 31) { stage(buf ^ 1, (kc + 1) * 32); CP_WAIT(1); }
        else         { CP_WAIT(0); }
        __syncthreads();

        const float* A = As + buf * PTILE;
        const float* Bt = Bs + buf * PTILE;
#pragma unroll
        for (int ks = 0; ks < 4; ks++) {
            uint32_t a[4][4];
#pragma unroll
            for (int mt = 0; mt < 4; mt++) {
                int row = wm * 64 + mt * 16 + g;
                a[mt][0] = __float_as_uint(A[row * PAD + ks * 8 + tg]);
                a[mt][1] = __float_as_uint(A[(row + 8) * PAD + ks * 8 + tg]);
                a[mt][2] = __float_as_uint(A[row * PAD + ks * 8 + tg + 4]);
                a[mt][3] = __float_as_uint(A[(row + 8) * PAD + ks * 8 + tg + 4]);
            }
#pragma unroll
            for (int nt = 0; nt < 8; nt++) {
                int n = wn * 64 + nt * 8 + g;
                uint32_t b0 = __float_as_uint(Bt[n * PAD + ks * 8 + tg]);
                uint32_t b1 = __float_as_uint(Bt[n * PAD + ks * 8 + tg + 4]);
#pragma unroll
                for (int mt = 0; mt < 4; mt++) mma8(acc[mt][nt], a[mt], b0, b1);
            }
        }
        __syncthreads();
    }

    float* base = (m3 == 0) ? g_q : ((m3 == 1) ? g_k : g_v);
#pragma unroll
    for (int mt = 0; mt < 4; mt++) {
        int row = wm * 64 + mt * 16 + g;
        int t = tt * 128 + row;
#pragma unroll
        for (int nt = 0; nt < 8; nt++) {
            int col = wn * 64 + nt * 8 + tg * 2;
            int hsel = col >> 6, d = col & 63;
            int bh = b * H_ + hp * 2 + hsel;
            float* dst = base + ((size_t)bh * T_ + t) * HS + d;
            *(float2*)dst = make_float2(tf32f(acc[mt][nt][0]), tf32f(acc[mt][nt][1]));
            *(float2*)(dst + 8 * HS) = make_float2(tf32f(acc[mt][nt][2]), tf32f(acc[mt][nt][3]));
        }
    }
}

// ---------------- attn3: 128-row Q tile, 4 warps x 32 rows, double-buffered KV ----------------
#define KPAD 68
#define VPAD 72
#define KTS (64 * KPAD)
#define VTS (64 * VPAD)
#define KV_STRIDE (KTS + VTS)
#define PS_OFF (2 * KV_STRIDE)
#define PPAD 68
#define ATTN_SMEM ((PS_OFF + 128 * PPAD) * 4)

__global__ __launch_bounds__(128) void attn3(float* __restrict__ out)
{
    extern __shared__ float sm[];
    uint32_t sbase = smem_u32(sm);
    float* Ps = sm + PS_OFF;

    const int qt = (int)gridDim.x - 1 - (int)blockIdx.x;   // heavy blocks first
    const int bh = blockIdx.y, b = bh >> 4, h = bh & 15;
    const int tid = threadIdx.x, warp = tid >> 5, lane = tid & 31;
    const int g = lane >> 2, tg = lane & 3;
    const int r0 = warp * 32 + g;

    const float* qb = g_q + ((size_t)bh * T_ + qt * 128) * HS;
    const float* kb = g_k + (size_t)bh * T_ * HS;
    const float* vb = g_v + (size_t)bh * T_ * HS;

    // Q fragments: warp rows r0+mt*16, r0+mt*16+8 for mt=0,1; scaled by 1/8
    uint32_t qf[8][2][4];
#pragma unroll
    for (int ks = 0; ks < 8; ks++)
#pragma unroll
        for (int mt = 0; mt < 2; mt++) {
            int row = r0 + mt * 16;
            qf[ks][mt][0] = f2tf32(qb[(size_t)row * HS + ks * 8 + tg] * 0.125f);
            qf[ks][mt][1] = f2tf32(qb[(size_t)(row + 8) * HS + ks * 8 + tg] * 0.125f);
            qf[ks][mt][2] = f2tf32(qb[(size_t)row * HS + ks * 8 + tg + 4] * 0.125f);
            qf[ks][mt][3] = f2tf32(qb[(size_t)(row + 8) * HS + ks * 8 + tg + 4] * 0.125f);
        }

    float mrun[4] = {-1e30f, -1e30f, -1e30f, -1e30f};
    float lrun[4] = {0.f, 0.f, 0.f, 0.f};
    float oacc[2][8][4];
#pragma unroll
    for (int mt = 0; mt < 2; mt++)
#pragma unroll
        for (int nt = 0; nt < 8; nt++)
#pragma unroll
            for (int e = 0; e < 4; e++) oacc[mt][nt][e] = 0.f;

    auto stageKV = [&](int buf, int j) {
        const float* kp = kb + (size_t)j * 64 * HS;
        const float* vp = vb + (size_t)j * 64 * HS;
        uint32_t ko = sbase + (buf * KV_STRIDE) * 4;
        uint32_t vo = ko + KTS * 4;
#pragma unroll
        for (int i = 0; i < 8; i++) {
            int fid = tid + i * 128;
            int r = fid >> 4, cc = (fid & 15) * 4;
            cp16(ko + (r * KPAD + cc) * 4, kp + (size_t)r * HS + cc);
            cp16(vo + (r * VPAD + cc) * 4, vp + (size_t)r * HS + cc);
        }
        CP_COMMIT();
    };

    const int jmax = 2 * qt + 2;
    stageKV(0, 0);
    for (int j = 0; j < jmax; j++) {
        const int buf = j & 1;
        if (j + 1 < jmax) { stageKV(buf ^ 1, j + 1); CP_WAIT(1); }
        else              { CP_WAIT(0); }
        __syncthreads();

        const float* Ks = sm + buf * KV_STRIDE;
        const float* Vs = Ks + KTS;

        // S = Q K^T : 32 Q rows x 64 KV cols per warp
        float sacc[2][8][4];
#pragma unroll
        for (int mt = 0; mt < 2; mt++)
#pragma unroll
            for (int nt = 0; nt < 8; nt++)
#pragma unroll
                for (int e = 0; e < 4; e++) sacc[mt][nt][e] = 0.f;
#pragma unroll
        for (int ks = 0; ks < 8; ks++) {
#pragma unroll
            for (int nt = 0; nt < 8; nt++) {
                uint32_t b0 = __float_as_uint(Ks[(nt * 8 + g) * KPAD + ks * 8 + tg]);
                uint32_t b1 = __float_as_uint(Ks[(nt * 8 + g) * KPAD + ks * 8 + tg + 4]);
                mma8(sacc[0][nt], qf[ks][0], b0, b1);
                mma8(sacc[1][nt], qf[ks][1], b0, b1);
            }
        }

        // Causal mask (only on tiles that can cross the diagonal for this warp/mt)
#pragma unroll
        for (int mt = 0; mt < 2; mt++) {
            if (j * 64 + 63 > qt * 128 + warp * 32 + mt * 16) {
#pragma unroll
                for (int nt = 0; nt < 8; nt++)
#pragma unroll
                    for (int e = 0; e < 2; e++) {
                        int colg = j * 64 + nt * 8 + tg * 2 + e;
                        int rowg = qt * 128 + r0 + mt * 16;
                        if (colg > rowg)     sacc[mt][nt][e]     = -1e30f;
                        if (colg > rowg + 8) sacc[mt][nt][2 + e] = -1e30f;
                    }
            }
        }

        // In-register online softmax per (mt, half)
#pragma unroll
        for (int mt = 0; mt < 2; mt++) {
            float mx0 = -1e30f, mx1 = -1e30f;
#pragma unroll
            for (int nt = 0; nt < 8; nt++) {
                mx0 = fmaxf(mx0, fmaxf(sacc[mt][nt][0], sacc[mt][nt][1]));
                mx1 = fmaxf(mx1, fmaxf(sacc[mt][nt][2], sacc[mt][nt][3]));
            }
            mx0 = fmaxf(mx0, __shfl_xor_sync(0xffffffffu, mx0, 1));
            mx0 = fmaxf(mx0, __shfl_xor_sync(0xffffffffu, mx0, 2));
            mx1 = fmaxf(mx1, __shfl_xor_sync(0xffffffffu, mx1, 1));
            mx1 = fmaxf(mx1, __shfl_xor_sync(0xffffffffu, mx1, 2));

            float mn0 = fmaxf(mrun[mt * 2], mx0);
            float mn1 = fmaxf(mrun[mt * 2 + 1], mx1);
            float al0 = __expf(mrun[mt * 2] - mn0);
            float al1 = __expf(mrun[mt * 2 + 1] - mn1);
            float ls0 = 0.f, ls1 = 0.f;
#pragma unroll
            for (int nt = 0; nt < 8; nt++) {
                float p0 = __expf(sacc[mt][nt][0] - mn0);
                float p1 = __expf(sacc[mt][nt][1] - mn0);
                float p2 = __expf(sacc[mt][nt][2] - mn1);
                float p3 = __expf(sacc[mt][nt][3] - mn1);
                sacc[mt][nt][0] = p0; sacc[mt][nt][1] = p1;
                sacc[mt][nt][2] = p2; sacc[mt][nt][3] = p3;
                ls0 += p0 + p1; ls1 += p2 + p3;
            }
            ls0 += __shfl_xor_sync(0xffffffffu, ls0, 1);
            ls0 += __shfl_xor_sync(0xffffffffu, ls0, 2);
            ls1 += __shfl_xor_sync(0xffffffffu, ls1, 1);
            ls1 += __shfl_xor_sync(0xffffffffu, ls1, 2);
            lrun[mt * 2]     = al0 * lrun[mt * 2] + ls0;
            lrun[mt * 2 + 1] = al1 * lrun[mt * 2 + 1] + ls1;
            mrun[mt * 2] = mn0; mrun[mt * 2 + 1] = mn1;
#pragma unroll
            for (int nt = 0; nt < 8; nt++) {
                oacc[mt][nt][0] *= al0; oacc[mt][nt][1] *= al0;
                oacc[mt][nt][2] *= al1; oacc[mt][nt][3] *= al1;
            }
        }

        // Warp-private P transpose through smem
#pragma unroll
        for (int mt = 0; mt < 2; mt++)
#pragma unroll
            for (int nt = 0; nt < 8; nt++) {
                int cc = nt * 8 + tg * 2;
                int row = r0 + mt * 16;
                *(float2*)(&Ps[row * PPAD + cc]) = make_float2(sacc[mt][nt][0], sacc[mt][nt][1]);
                *(float2*)(&Ps[(row + 8) * PPAD + cc]) = make_float2(sacc[mt][nt][2], sacc[mt][nt][3]);
            }
        __syncwarp();

        // O += P V
#pragma unroll
        for (int ks = 0; ks < 8; ks++) {
            uint32_t pa[2][4];
#pragma unroll
            for (int mt = 0; mt < 2; mt++) {
                int row = r0 + mt * 16;
                pa[mt][0] = f2tf32(Ps[row * PPAD + ks * 8 + tg]);
                pa[mt][1] = f2tf32(Ps[(row + 8) * PPAD + ks * 8 + tg]);
                pa[mt][2] = f2tf32(Ps[row * PPAD + ks * 8 + tg + 4]);
                pa[mt][3] = f2tf32(Ps[(row + 8) * PPAD + ks * 8 + tg + 4]);
            }
#pragma unroll
            for (int nt = 0; nt < 8; nt++) {
                uint32_t b0 = __float_as_uint(Vs[(ks * 8 + tg) * VPAD + nt * 8 + g]);
                uint32_t b1 = __float_as_uint(Vs[(ks * 8 + tg + 4) * VPAD + nt * 8 + g]);
                mma8(oacc[0][nt], pa[0], b0, b1);
                mma8(oacc[1][nt], pa[1], b0, b1);
            }
        }
        __syncthreads();
    }

    // Normalize + write
#pragma unroll
    for (int mt = 0; mt < 2; mt++) {
        float inv0 = 1.0f / lrun[mt * 2];
        float inv1 = 1.0f / lrun[mt * 2 + 1];
        int row = qt * 128 + r0 + mt * 16;
        float* op = out + ((size_t)(b * T_ + row)) * (H_ * HS) + h * HS;
#pragma unroll
        for (int nt = 0; nt < 8; nt++) {
            int cc = nt * 8 + tg * 2;
            *(float2*)(op + cc) =
                make_float2(oacc[mt][nt][0] * inv0, oacc[mt][nt][1] * inv0);
            *(float2*)(op + (size_t)8 * (H_ * HS) + cc) =
                make_float2(oacc[mt][nt][2] * inv1, oacc[mt][nt][3] * inv1);
        }
    }
}

// ---------------------------------------------------------------------------
extern "C" void kernel_launch(void* const* d_in, const int* in_sizes, int n_in,
                              void* d_out, int out_size)
{
    const float* x  = (const float*)d_in[0];
    const float* Wq = (const float*)d_in[1];
    const float* Wk = (const float*)d_in[2];
    const float* Wv = (const float*)d_in[3];
    float* out = (float*)d_out;

    xprep<<<(B_ * T_ * C_) / 1024, 256>>>(x);
    wprep<<<dim3(16, 48), 256>>>(Wq, Wk, Wv);

    int psmem = 4 * PTILE * (int)sizeof(float);
    cudaFuncSetAttribute(proj3, cudaFuncAttributeMaxDynamicSharedMemorySize, psmem);
    proj3<<<dim3(64, 24), 128, psmem>>>();

    cudaFuncSetAttribute(attn3, cudaFuncAttributeMaxDynamicSharedMemorySize, ATTN_SMEM);
    attn3<<<dim3(T_ / 128, B_ * H_), 128, ATTN_SMEM>>>(out);
}